// round 12
// baseline (speedup 1.0000x reference)
#include <cuda_runtime.h>
#include <math.h>

#define Bc 4
#define Sc 2
#define Pc 17
#define Wc 128
#define Mc 8
#define Kc 10
#define Cc 34          // (1+TAG)*P
#define HWc 16384
#define BSc 8
#define DET_N (Bc*Sc*Pc*HWc)
#define NCH 34
#define CHUNK 8192
#define NITEM (BSc*Kc*Pc)   // 1360
#define PLN (Pc*BSc)        // 136 planes
#define NBLKA (NCH*BSc)     // 272 scan blocks

// ---------------- scratch (device globals) ----------------
__device__ double g_det_part[BSc*NCH];
__device__ float  g_cand_v[BSc*NCH*Kc];
__device__ int    g_cand_i[BSc*NCH*Kc];
__device__ float  g_tv[BSc*Kc];
__device__ int    g_pid[BSc*Kc];
__device__ double g_hubpart[PLN];
__device__ double g_pushpull[2];
__device__ double g_dettot;
__device__ int    g_cnt1 = 0;
__device__ int    g_cnt2 = 0;

#define EINV 0.36787944117144233f

// single-MUFU exp2
__device__ __forceinline__ float ex2(float x) {
    float r;
    asm("ex2.approx.ftz.f32 %0, %1;" : "=f"(r) : "f"(x));
    return r;
}

// monotone float -> orderable uint
__device__ __forceinline__ unsigned ford(float f) {
    unsigned b = __float_as_uint(f);
    return b ^ ((b & 0x80000000u) ? 0xFFFFFFFFu : 0x80000000u);
}

// branchless register-resident top-10 insertion
__device__ __forceinline__ void insert10(float val, int idx, float* v, int* ix) {
    if (val <= v[Kc - 1]) return;
#pragma unroll
    for (int k = Kc - 1; k > 0; k--) {
        bool shift = val > v[k - 1];
        bool place = val > v[k];
        float nv = shift ? v[k - 1] : (place ? val : v[k]);
        int   ni = shift ? ix[k - 1] : (place ? idx : ix[k]);
        v[k] = nv; ix[k] = ni;
    }
    if (val > v[0]) { v[0] = val; ix[0] = idx; }
}

// ============================================================
// Kernel A: det-BCE + per-chunk top-10 (round-8 fast body);
// LAST block runs the aux tail ONCE (redux merge + push/pull +
// tv/pid + det total) so kernel B needs no prologue.
// grid (NCH, BSc) = 272 blocks x 512 threads
// ============================================================
__global__ void __launch_bounds__(512, 2)
scan_kernel(const float* __restrict__ preds,
            const float* __restrict__ gt_masks,
            const float* __restrict__ gt_heatmaps,
            const float* __restrict__ gt_sk,
            const int* __restrict__ gt_kp) {
    int ch = blockIdx.x;            // 0..33 : p = ch>>1, half = ch&1
    int bs = blockIdx.y;
    int tid = threadIdx.x;
    int w = tid >> 5;
    int lane = tid & 31;
    int p    = ch >> 1;
    int hw0  = (ch & 1) * CHUNK;
    int b    = bs >> 1;

    const float4* __restrict__ hm4 = (const float4*)(preds + ((size_t)bs * Cc + p) * HWc + hw0);
    const float4* __restrict__ gh4 = (const float4*)(gt_heatmaps + ((size_t)(b * Pc + p)) * HWc + hw0);
    const float4* __restrict__ mk4 = (const float4*)(gt_masks + (size_t)b * HWc + hw0);
    int i0 = ch * CHUNK;

    float v[Kc]; int ix[Kc];
#pragma unroll
    for (int k = 0; k < Kc; k++) { v[k] = -3.0e38f; ix[k] = -1; }
    float facc = 0.0f;

#pragma unroll
    for (int j = 0; j < 4; j++) {
        int idx4 = tid + 512 * j;
        float4 f = hm4[idx4];
        float4 g = gh4[idx4];
        float4 m = mk4[idx4];
        int e = i0 + 4 * idx4;
        insert10(f.x, e + 0, v, ix);
        insert10(f.y, e + 1, v, ix);
        insert10(f.z, e + 2, v, ix);
        insert10(f.w, e + 3, v, ix);
        float hs[4] = {f.x, f.y, f.z, f.w};
        float gs[4] = {g.x, g.y, g.z, g.w};
        float ms[4] = {m.x, m.y, m.z, m.w};
#pragma unroll
        for (int c = 0; c < 4; c++) {
            float prob = __fdividef(1.0f, 1.0f + __expf(-hs[c]));
            float x = prob * ms[c];
            bool selp = gs[c] > EINV;
            float wv  = selp ? 10.0f : ((gs[c] < EINV) ? 0.5f : 0.0f);
            float arg = selp ? x : (1.0f - x);
            facc -= wv * fmaxf(__logf(arg), -100.0f);
        }
    }

    // det: warp reduce float, then serial double over 16 warps
    __shared__ float sdet[16];
#pragma unroll
    for (int o = 16; o > 0; o >>= 1) facc += __shfl_xor_sync(0xffffffffu, facc, o);
    if (lane == 0) sdet[w] = facc;

    // per-warp top-10 via redux argmax (no barriers)
    __shared__ float swv[160];
    __shared__ int   swi[160];
    for (int sel = 0; sel < Kc; sel++) {
        float bv = v[0]; int bidx = ix[0]; int bslot = 0;
#pragma unroll
        for (int j = 1; j < Kc; j++)
            if (v[j] > bv) { bv = v[j]; bidx = ix[j]; bslot = j; }
        unsigned ub = ford(bv);
        unsigned mx = __reduce_max_sync(0xffffffffu, ub);
        unsigned msk = __ballot_sync(0xffffffffu, ub == mx);
        int leader = __ffs(msk) - 1;
        if (lane == leader) {
            swv[w * Kc + sel] = bv;
            swi[w * Kc + sel] = bidx;
#pragma unroll
            for (int j = 0; j < Kc; j++)
                if (j == bslot) v[j] = -3.1e38f;
        }
    }
    __syncthreads();

    // warp 0: merge 160 candidates -> block top-10 (+ det partial)
    if (w == 0) {
        float cv[5]; int ci[5];
#pragma unroll
        for (int t = 0; t < 5; t++) {
            cv[t] = swv[lane * 5 + t];
            ci[t] = swi[lane * 5 + t];
        }
        for (int sel = 0; sel < Kc; sel++) {
            float bv = cv[0]; int bidx = ci[0]; int bslot = 0;
#pragma unroll
            for (int t = 1; t < 5; t++)
                if (cv[t] > bv) { bv = cv[t]; bidx = ci[t]; bslot = t; }
            unsigned ub = ford(bv);
            unsigned mx = __reduce_max_sync(0xffffffffu, ub);
            unsigned msk = __ballot_sync(0xffffffffu, ub == mx);
            int leader = __ffs(msk) - 1;
            if (lane == leader) {
                int slot = (bs * NCH + ch) * Kc + sel;
                g_cand_v[slot] = bv;
                g_cand_i[slot] = bidx;
#pragma unroll
                for (int t = 0; t < 5; t++)
                    if (t == bslot) cv[t] = -3.1e38f;
            }
        }
        if (lane == 0) {
            double d = 0.0;
#pragma unroll
            for (int j = 0; j < 16; j++) d += (double)sdet[j];
            g_det_part[bs * NCH + ch] = d;
        }
    }

    // ================= last-block aux tail (ONCE) =================
    __threadfence();
    __shared__ int isLast;
    if (tid == 0) isLast = (atomicAdd(&g_cnt1, 1) == NBLKA - 1) ? 1 : 0;
    __syncthreads();
    if (!isLast) return;
    __threadfence();

    __shared__ int   stopi[BSc * Kc];
    __shared__ float spush[BSc], spull[BSc];

    if (w < BSc) {
        // ---- redux merge: 340 candidates -> top-10 for bs = w ----
        int mbs = w;
        float cv[11]; int ci[11];
#pragma unroll
        for (int j = 0; j < 11; j++) {
            int c = lane * 11 + j;
            if (c < NCH * Kc) {
                cv[j] = g_cand_v[mbs * NCH * Kc + c];
                ci[j] = g_cand_i[mbs * NCH * Kc + c];
            } else { cv[j] = -3.3e38f; ci[j] = -1; }
        }
        for (int sel = 0; sel < Kc; sel++) {
            float bv = cv[0]; int bidx = ci[0]; int bslot = 0;
#pragma unroll
            for (int j = 1; j < 11; j++)
                if (cv[j] > bv) { bv = cv[j]; bidx = ci[j]; bslot = j; }
            unsigned ub = ford(bv);
            unsigned mx = __reduce_max_sync(0xffffffffu, ub);
            unsigned msk = __ballot_sync(0xffffffffu, ub == mx);
            int leader = __ffs(msk) - 1;
            if (lane == leader) {
                stopi[mbs * Kc + sel] = bidx;
#pragma unroll
                for (int j = 0; j < 11; j++)
                    if (j == bslot) cv[j] = -3.3e38f;
            }
        }
    } else {
        // ---- push/pull for bs = w-8 (lane = m*4 + q) ----
        int mbs = w - BSc;
        int mb  = mbs / Sc;
        int m  = lane >> 2;
        int q  = lane & 3;
        int np = (q == 0) ? 5 : 4;
        const float* tb = preds + ((size_t)mbs * Cc + Pc) * HWc;
        const int* kpb = gt_kp + ((mb * Mc + m) * Pc) * 2;

        float gv[5], vv[5];
        float cnt = 0.0f, sum = 0.0f;
#pragma unroll
        for (int i = 0; i < 5; i++) {
            gv[i] = 0.0f; vv[i] = 0.0f;
            if (i < np) {
                int pp2 = q + 4 * i;
                int idx  = kpb[2 * pp2];
                float vis = (kpb[2 * pp2 + 1] > 0) ? 1.0f : 0.0f;
                float g = tb[idx];
                gv[i] = g; vv[i] = vis;
                cnt += vis; sum += vis * g;
            }
        }
        cnt += __shfl_xor_sync(0xffffffffu, cnt, 1);
        cnt += __shfl_xor_sync(0xffffffffu, cnt, 2);
        sum += __shfl_xor_sync(0xffffffffu, sum, 1);
        sum += __shfl_xor_sync(0xffffffffu, sum, 2);
        float valid = (cnt > 0.0f) ? 1.0f : 0.0f;
        float safe  = fmaxf(cnt, 1.0f);
        float mean  = sum / safe;
        float pp = 0.0f;
#pragma unroll
        for (int i = 0; i < 5; i++) {
            float d = gv[i] - mean;
            pp += d * d * vv[i];
        }
        pp += __shfl_xor_sync(0xffffffffu, pp, 1);
        pp += __shfl_xor_sync(0xffffffffu, pp, 2);
        float pull_m = (pp / safe) * valid;
        float num = valid, pullsum = pull_m;
#pragma unroll
        for (int o = 4; o <= 16; o <<= 1) {
            num     += __shfl_xor_sync(0xffffffffu, num, o);
            pullsum += __shfl_xor_sync(0xffffffffu, pullsum, o);
        }
        float rowsum = 0.0f;
#pragma unroll
        for (int jj = 0; jj < 2; jj++) {
            int j = q + 4 * jj;
            float mj = __shfl_sync(0xffffffffu, mean, j * 4);
            float vj = __shfl_sync(0xffffffffu, valid, j * 4);
            float d = mean - mj;
            rowsum += __expf(-d * d) * valid * vj;
        }
        rowsum += __shfl_xor_sync(0xffffffffu, rowsum, 1);
        rowsum += __shfl_xor_sync(0xffffffffu, rowsum, 2);
        float pmsum = rowsum;
#pragma unroll
        for (int o = 4; o <= 16; o <<= 1)
            pmsum += __shfl_xor_sync(0xffffffffu, pmsum, o);
        if (lane == 0) {
            spush[mbs] = (pmsum - num) / ((num - 1.0f) * num + 1e-6f) * 0.5f;
            spull[mbs] = pullsum / (num + 1e-6f);
        }
    }
    __syncthreads();

    // ---- tv & person_ids + det total ----
    double dacc = 0.0;
    for (int j = tid; j < BSc * NCH; j += 512) dacc += g_det_part[j];
    if (tid < BSc * Kc) {
        int tbs = tid / Kc;
        int tb  = tbs / Sc;
        int i  = stopi[tid];
        int tp = i / HWc;
        int hw = i % HWc;
        int xi = hw / Wc;
        int yi = hw % Wc;
        g_tv[tid] = preds[((size_t)tbs * Cc + Pc) * HWc + i];
        float best = 3.4e38f; int bestm = 0;
        for (int m = 0; m < Mc; m++) {
            const float* sk = gt_sk + ((tb * Mc + m) * Pc + tp) * 3;
            float vp = (sk[2] == 1.0f) ? 256.0f : 0.0f;
            float d0 = vp + sk[1] - (float)xi;
            float d1 = vp + sk[2] - (float)yi;
            float d  = sqrtf(d0 * d0 + d1 * d1 + 1e-12f);
            if (d < best) { best = d; bestm = m; }
        }
        g_pid[tid] = bestm;
    }
    __shared__ double dred[512];
    dred[tid] = dacc;
    __syncthreads();
    for (int o = 256; o > 0; o >>= 1) {
        if (tid < o) dred[tid] += dred[tid + o];
        __syncthreads();
    }
    if (tid == 0) {
        g_dettot = dred[0];
        double sp = 0.0, sl = 0.0;
        for (int j = 0; j < BSc; j++) { sp += (double)spush[j]; sl += (double)spull[j]; }
        g_pushpull[0] = sp;
        g_pushpull[1] = sl;
        g_cnt1 = 0;          // reset for graph replay
    }
}

// ============================================================
// Kernel B: PROLOGUE-FREE softmax: one block per (bs,p) plane,
// read-once, all 10 k in registers, row-factored + ex2 math.
// Fused Huber; last block combines. grid (Pc, BSc) x 512.
// ============================================================
__global__ void __launch_bounds__(512)
softhub_kernel(const float* __restrict__ preds,
               const float* __restrict__ gt_sk,
               float* __restrict__ out) {
    int p  = blockIdx.x;
    int bs = blockIdx.y;
    int tid = threadIdx.x;
    int w = tid >> 5;
    int lane = tid & 31;
    int b  = bs >> 1;

    __shared__ float  stv[Kc];
    __shared__ int    spid[Kc];
    __shared__ float  swarp[16][3 * Kc];
    __shared__ float  tot[3 * Kc];
    __shared__ double shub[Kc];
    __shared__ int    isLast;
    __shared__ double dred[512];

    if (tid < Kc) {
        stv[tid]  = g_tv[bs * Kc + tid];
        spid[tid] = g_pid[bs * Kc + tid];
    }
    __syncthreads();

    const float4* __restrict__ hm4 = (const float4*)(preds + ((size_t)bs * Cc + p) * HWc);
    const float4* __restrict__ tg4 = hm4 + (Pc * HWc / 4);

    const float C1 = 4.328085122666891f;     // 3 * log2(e)
    const float C2 = 18.033688011112047f;    // 12.5 * log2(e)
    const float TWOC2 = 36.067376022224094f;
    float hmax = fmaxf(g_cand_v[(bs * NCH + 2 * p) * Kc],
                       g_cand_v[(bs * NCH + 2 * p + 1) * Kc]);
    float L = C1 * hmax;

    float tv[Kc], tvq[Kc];
#pragma unroll
    for (int k = 0; k < Kc; k++) {
        float t = stv[k];
        tv[k] = t;
        tvq[k] = -C2 * t * t;
    }

    float se[Kc], sx[Kc], sy[Kc];
#pragma unroll
    for (int k = 0; k < Kc; k++) { se[k] = 0.0f; sx[k] = 0.0f; sy[k] = 0.0f; }

#pragma unroll 2
    for (int j = 0; j < 8; j++) {
        int idx4 = tid + 512 * j;
        float4 h = hm4[idx4];
        float4 t = tg4[idx4];
        int e0 = 4 * idx4;
        float xf = (float)(e0 >> 7);          // row constant within float4
        float yb = (float)(e0 & 127);
        float b0 = fmaf(C1, h.x, -L), b1 = fmaf(C1, h.y, -L);
        float b2 = fmaf(C1, h.z, -L), b3 = fmaf(C1, h.w, -L);
        float A0 = fmaf(t.x * (-C2), t.x, b0), B0 = t.x * TWOC2;
        float A1 = fmaf(t.y * (-C2), t.y, b1), B1 = t.y * TWOC2;
        float A2_ = fmaf(t.z * (-C2), t.z, b2), B2 = t.z * TWOC2;
        float A3 = fmaf(t.w * (-C2), t.w, b3), B3 = t.w * TWOC2;
#pragma unroll
        for (int k = 0; k < Kc; k++) {
            float e0f = ex2(fmaf(B0, tv[k], A0) + tvq[k]);
            float e1f = ex2(fmaf(B1, tv[k], A1) + tvq[k]);
            float e2f = ex2(fmaf(B2, tv[k], A2_) + tvq[k]);
            float e3f = ex2(fmaf(B3, tv[k], A3) + tvq[k]);
            float srow = (e0f + e1f) + (e2f + e3f);
            se[k] += srow;
            sx[k] = fmaf(srow, xf, sx[k]);
            float u = fmaf(e2f, 2.0f, e1f);
            u = fmaf(e3f, 3.0f, u);
            sy[k] = fmaf(srow, yb, sy[k]);
            sy[k] += u;
        }
    }

#pragma unroll
    for (int o = 16; o > 0; o >>= 1) {
#pragma unroll
        for (int k = 0; k < Kc; k++) {
            se[k] += __shfl_xor_sync(0xffffffffu, se[k], o);
            sx[k] += __shfl_xor_sync(0xffffffffu, sx[k], o);
            sy[k] += __shfl_xor_sync(0xffffffffu, sy[k], o);
        }
    }
    if (lane == 0) {
#pragma unroll
        for (int k = 0; k < Kc; k++) {
            swarp[w][k]          = se[k];
            swarp[w][Kc + k]     = sx[k];
            swarp[w][2 * Kc + k] = sy[k];
        }
    }
    __syncthreads();
    if (tid < 3 * Kc) {
        float s = 0.0f;
#pragma unroll
        for (int ww = 0; ww < 16; ww++) s += swarp[ww][tid];
        tot[tid] = s;
    }
    __syncthreads();

    // Huber for all 10 ks
    if (tid < Kc) {
        float seT = tot[tid], sxT = tot[Kc + tid], syT = tot[2 * Kc + tid];
        float inv = 1.0f / seT;
        float px = sxT * inv, py = syT * inv;
        int pid = spid[tid];
        const float* sk = gt_sk + ((b * Mc + pid) * Pc + p) * 3;
        float ex = sk[0] - px;
        float ey = sk[1] - py;
        float err = sqrtf(ex * ex + ey * ey + 1e-12f) * ((sk[2] > 0.0f) ? 1.0f : 0.0f);
        float a = fabsf(err);
        shub[tid] = (double)((a < 0.1f) ? (err * err) : (0.1f * (a - 0.05f)));
    }
    __syncthreads();
    if (tid == 0) {
        double s = 0.0;
#pragma unroll
        for (int k = 0; k < Kc; k++) s += shub[k];
        g_hubpart[bs * Pc + p] = s;
    }

    // ---- last block: final combine ----
    __threadfence();
    if (tid == 0) isLast = (atomicAdd(&g_cnt2, 1) == PLN - 1) ? 1 : 0;
    __syncthreads();
    if (!isLast) return;
    __threadfence();

    double hacc = 0.0;
    for (int j = tid; j < PLN; j += 512) hacc += g_hubpart[j];
    dred[tid] = hacc;
    __syncthreads();
    for (int o = 256; o > 0; o >>= 1) {
        if (tid < o) dred[tid] += dred[tid + o];
        __syncthreads();
    }
    if (tid == 0) {
        double det = g_dettot / (double)DET_N;
        double total = g_pushpull[0] / 8.0
                     + g_pushpull[1] / 8.0
                     + det
                     + 10.0 * dred[0] / (double)NITEM;
        out[0] = (float)total;
        g_cnt2 = 0;           // reset for graph replay
    }
}

// ============================================================
extern "C" void kernel_launch(void* const* d_in, const int* in_sizes, int n_in,
                              void* d_out, int out_size) {
    const float* preds       = (const float*)d_in[0];
    const float* gt_masks    = (const float*)d_in[1];
    const float* gt_heatmaps = (const float*)d_in[2];
    const float* gt_sk       = (const float*)d_in[3];
    const int*   gt_kp       = (const int*)d_in[4];

    scan_kernel<<<dim3(NCH, BSc), 512>>>(preds, gt_masks, gt_heatmaps, gt_sk, gt_kp);
    softhub_kernel<<<dim3(Pc, BSc), 512>>>(preds, gt_sk, (float*)d_out);
}

// round 13
// speedup vs baseline: 1.0642x; 1.0642x over previous
#include <cuda_runtime.h>
#include <math.h>

#define Bc 4
#define Sc 2
#define Pc 17
#define Wc 128
#define Mc 8
#define Kc 10
#define Cc 34          // (1+TAG)*P
#define HWc 16384
#define BSc 8
#define DET_N (Bc*Sc*Pc*HWc)
#define NCH 34
#define CHUNK 8192
#define NITEM (BSc*Kc*Pc)   // 1360
#define PLN (Pc*BSc)        // 136 planes

// ---------------- scratch (device globals) ----------------
__device__ double g_det_part[BSc*NCH];
__device__ float  g_cand_v[BSc*NCH*Kc];
__device__ int    g_cand_i[BSc*NCH*Kc];
__device__ float  g_tv[BSc*Kc];
__device__ int    g_pid[BSc*Kc];
__device__ double g_hubpart[PLN];
__device__ double g_pushpull[2];
__device__ int    g_cnt2 = 0;

#define EINV 0.36787944117144233f

// single-MUFU exp2
__device__ __forceinline__ float ex2(float x) {
    float r;
    asm("ex2.approx.ftz.f32 %0, %1;" : "=f"(r) : "f"(x));
    return r;
}

// monotone float -> orderable uint
__device__ __forceinline__ unsigned ford(float f) {
    unsigned b = __float_as_uint(f);
    return b ^ ((b & 0x80000000u) ? 0xFFFFFFFFu : 0x80000000u);
}

// branchless register-resident top-10 insertion
__device__ __forceinline__ void insert10(float val, int idx, float* v, int* ix) {
    if (val <= v[Kc - 1]) return;
#pragma unroll
    for (int k = Kc - 1; k > 0; k--) {
        bool shift = val > v[k - 1];
        bool place = val > v[k];
        float nv = shift ? v[k - 1] : (place ? val : v[k]);
        int   ni = shift ? ix[k - 1] : (place ? idx : ix[k]);
        v[k] = nv; ix[k] = ni;
    }
    if (val > v[0]) { v[0] = val; ix[0] = idx; }
}

// ============================================================
// Kernel A: det-BCE partials + per-chunk top-10 (R8 proven body,
// NO tail). grid (NCH, BSc) = 272 blocks x 512 threads.
// ============================================================
__global__ void __launch_bounds__(512, 2)
scan_kernel(const float* __restrict__ preds,
            const float* __restrict__ gt_masks,
            const float* __restrict__ gt_heatmaps) {
    int ch = blockIdx.x;            // 0..33 : p = ch>>1, half = ch&1
    int bs = blockIdx.y;
    int tid = threadIdx.x;
    int w = tid >> 5;
    int lane = tid & 31;
    int p    = ch >> 1;
    int hw0  = (ch & 1) * CHUNK;
    int b    = bs >> 1;

    const float4* __restrict__ hm4 = (const float4*)(preds + ((size_t)bs * Cc + p) * HWc + hw0);
    const float4* __restrict__ gh4 = (const float4*)(gt_heatmaps + ((size_t)(b * Pc + p)) * HWc + hw0);
    const float4* __restrict__ mk4 = (const float4*)(gt_masks + (size_t)b * HWc + hw0);
    int i0 = ch * CHUNK;

    float v[Kc]; int ix[Kc];
#pragma unroll
    for (int k = 0; k < Kc; k++) { v[k] = -3.0e38f; ix[k] = -1; }
    float facc = 0.0f;

#pragma unroll
    for (int j = 0; j < 4; j++) {
        int idx4 = tid + 512 * j;
        float4 f = hm4[idx4];
        float4 g = gh4[idx4];
        float4 m = mk4[idx4];
        int e = i0 + 4 * idx4;
        insert10(f.x, e + 0, v, ix);
        insert10(f.y, e + 1, v, ix);
        insert10(f.z, e + 2, v, ix);
        insert10(f.w, e + 3, v, ix);
        float hs[4] = {f.x, f.y, f.z, f.w};
        float gs[4] = {g.x, g.y, g.z, g.w};
        float ms[4] = {m.x, m.y, m.z, m.w};
#pragma unroll
        for (int c = 0; c < 4; c++) {
            float prob = __fdividef(1.0f, 1.0f + __expf(-hs[c]));
            float x = prob * ms[c];
            bool selp = gs[c] > EINV;
            float wv  = selp ? 10.0f : ((gs[c] < EINV) ? 0.5f : 0.0f);
            float arg = selp ? x : (1.0f - x);
            facc -= wv * fmaxf(__logf(arg), -100.0f);
        }
    }

    // det: warp reduce float, then serial double over 16 warps
    __shared__ float sdet[16];
#pragma unroll
    for (int o = 16; o > 0; o >>= 1) facc += __shfl_xor_sync(0xffffffffu, facc, o);
    if (lane == 0) sdet[w] = facc;

    // per-warp top-10 via redux argmax (no barriers)
    __shared__ float swv[160];
    __shared__ int   swi[160];
    for (int sel = 0; sel < Kc; sel++) {
        float bv = v[0]; int bidx = ix[0]; int bslot = 0;
#pragma unroll
        for (int j = 1; j < Kc; j++)
            if (v[j] > bv) { bv = v[j]; bidx = ix[j]; bslot = j; }
        unsigned ub = ford(bv);
        unsigned mx = __reduce_max_sync(0xffffffffu, ub);
        unsigned msk = __ballot_sync(0xffffffffu, ub == mx);
        int leader = __ffs(msk) - 1;
        if (lane == leader) {
            swv[w * Kc + sel] = bv;
            swi[w * Kc + sel] = bidx;
#pragma unroll
            for (int j = 0; j < Kc; j++)
                if (j == bslot) v[j] = -3.1e38f;
        }
    }
    __syncthreads();

    // warp 0: merge 160 candidates -> block top-10 (+ det partial)
    if (w == 0) {
        float cv[5]; int ci[5];
#pragma unroll
        for (int t = 0; t < 5; t++) {
            cv[t] = swv[lane * 5 + t];
            ci[t] = swi[lane * 5 + t];
        }
        for (int sel = 0; sel < Kc; sel++) {
            float bv = cv[0]; int bidx = ci[0]; int bslot = 0;
#pragma unroll
            for (int t = 1; t < 5; t++)
                if (cv[t] > bv) { bv = cv[t]; bidx = ci[t]; bslot = t; }
            unsigned ub = ford(bv);
            unsigned mx = __reduce_max_sync(0xffffffffu, ub);
            unsigned msk = __ballot_sync(0xffffffffu, ub == mx);
            int leader = __ffs(msk) - 1;
            if (lane == leader) {
                int slot = (bs * NCH + ch) * Kc + sel;
                g_cand_v[slot] = bv;
                g_cand_i[slot] = bidx;
#pragma unroll
                for (int t = 0; t < 5; t++)
                    if (t == bslot) cv[t] = -3.1e38f;
            }
        }
        if (lane == 0) {
            double d = 0.0;
#pragma unroll
            for (int j = 0; j < 16; j++) d += (double)sdet[j];
            g_det_part[bs * NCH + ch] = d;
        }
    }
}

// ============================================================
// Kernel B (tiny): aux — redux merge per bs (warps 0-7),
// push/pull (warps 8-15), then tv & person_ids.
// 1 block x 512 threads.
// ============================================================
__global__ void __launch_bounds__(512)
aux_kernel(const float* __restrict__ preds,
           const float* __restrict__ gt_sk,
           const int* __restrict__ gt_kp) {
    int tid = threadIdx.x;
    int w = tid >> 5;
    int lane = tid & 31;
    __shared__ int   stopi[BSc * Kc];
    __shared__ float spush[BSc], spull[BSc];

    if (w < BSc) {
        // ---- redux merge: 340 candidates -> top-10 for bs = w ----
        int mbs = w;
        float cv[11]; int ci[11];
#pragma unroll
        for (int j = 0; j < 11; j++) {
            int c = lane * 11 + j;
            if (c < NCH * Kc) {
                cv[j] = g_cand_v[mbs * NCH * Kc + c];
                ci[j] = g_cand_i[mbs * NCH * Kc + c];
            } else { cv[j] = -3.3e38f; ci[j] = -1; }
        }
        for (int sel = 0; sel < Kc; sel++) {
            float bv = cv[0]; int bidx = ci[0]; int bslot = 0;
#pragma unroll
            for (int j = 1; j < 11; j++)
                if (cv[j] > bv) { bv = cv[j]; bidx = ci[j]; bslot = j; }
            unsigned ub = ford(bv);
            unsigned mx = __reduce_max_sync(0xffffffffu, ub);
            unsigned msk = __ballot_sync(0xffffffffu, ub == mx);
            int leader = __ffs(msk) - 1;
            if (lane == leader) {
                stopi[mbs * Kc + sel] = bidx;
#pragma unroll
                for (int j = 0; j < 11; j++)
                    if (j == bslot) cv[j] = -3.3e38f;
            }
        }
    } else {
        // ---- push/pull for bs = w-8 (lane = m*4 + q) ----
        int mbs = w - BSc;
        int mb  = mbs / Sc;
        int m  = lane >> 2;
        int q  = lane & 3;
        int np = (q == 0) ? 5 : 4;
        const float* tb = preds + ((size_t)mbs * Cc + Pc) * HWc;
        const int* kpb = gt_kp + ((mb * Mc + m) * Pc) * 2;

        float gv[5], vv[5];
        float cnt = 0.0f, sum = 0.0f;
#pragma unroll
        for (int i = 0; i < 5; i++) {
            gv[i] = 0.0f; vv[i] = 0.0f;
            if (i < np) {
                int pp2 = q + 4 * i;
                int idx  = kpb[2 * pp2];
                float vis = (kpb[2 * pp2 + 1] > 0) ? 1.0f : 0.0f;
                float g = tb[idx];
                gv[i] = g; vv[i] = vis;
                cnt += vis; sum += vis * g;
            }
        }
        cnt += __shfl_xor_sync(0xffffffffu, cnt, 1);
        cnt += __shfl_xor_sync(0xffffffffu, cnt, 2);
        sum += __shfl_xor_sync(0xffffffffu, sum, 1);
        sum += __shfl_xor_sync(0xffffffffu, sum, 2);
        float valid = (cnt > 0.0f) ? 1.0f : 0.0f;
        float safe  = fmaxf(cnt, 1.0f);
        float mean  = sum / safe;
        float pp = 0.0f;
#pragma unroll
        for (int i = 0; i < 5; i++) {
            float d = gv[i] - mean;
            pp += d * d * vv[i];
        }
        pp += __shfl_xor_sync(0xffffffffu, pp, 1);
        pp += __shfl_xor_sync(0xffffffffu, pp, 2);
        float pull_m = (pp / safe) * valid;
        float num = valid, pullsum = pull_m;
#pragma unroll
        for (int o = 4; o <= 16; o <<= 1) {
            num     += __shfl_xor_sync(0xffffffffu, num, o);
            pullsum += __shfl_xor_sync(0xffffffffu, pullsum, o);
        }
        float rowsum = 0.0f;
#pragma unroll
        for (int jj = 0; jj < 2; jj++) {
            int j = q + 4 * jj;
            float mj = __shfl_sync(0xffffffffu, mean, j * 4);
            float vj = __shfl_sync(0xffffffffu, valid, j * 4);
            float d = mean - mj;
            rowsum += __expf(-d * d) * valid * vj;
        }
        rowsum += __shfl_xor_sync(0xffffffffu, rowsum, 1);
        rowsum += __shfl_xor_sync(0xffffffffu, rowsum, 2);
        float pmsum = rowsum;
#pragma unroll
        for (int o = 4; o <= 16; o <<= 1)
            pmsum += __shfl_xor_sync(0xffffffffu, pmsum, o);
        if (lane == 0) {
            spush[mbs] = (pmsum - num) / ((num - 1.0f) * num + 1e-6f) * 0.5f;
            spull[mbs] = pullsum / (num + 1e-6f);
        }
    }
    __syncthreads();

    // ---- tv & person_ids ----
    if (tid < BSc * Kc) {
        int tbs = tid / Kc;
        int tb  = tbs / Sc;
        int i  = stopi[tid];
        int tp = i / HWc;
        int hw = i % HWc;
        int xi = hw / Wc;
        int yi = hw % Wc;
        g_tv[tid] = preds[((size_t)tbs * Cc + Pc) * HWc + i];
        float best = 3.4e38f; int bestm = 0;
        for (int m = 0; m < Mc; m++) {
            const float* sk = gt_sk + ((tb * Mc + m) * Pc + tp) * 3;
            float vp = (sk[2] == 1.0f) ? 256.0f : 0.0f;
            float d0 = vp + sk[1] - (float)xi;
            float d1 = vp + sk[2] - (float)yi;
            float d  = sqrtf(d0 * d0 + d1 * d1 + 1e-12f);
            if (d < best) { best = d; bestm = m; }
        }
        g_pid[tid] = bestm;
    }
    if (tid == 128) {
        double sp = 0.0, sl = 0.0;
        for (int j = 0; j < BSc; j++) { sp += (double)spush[j]; sl += (double)spull[j]; }
        g_pushpull[0] = sp;
        g_pushpull[1] = sl;
    }
}

// ============================================================
// Kernel C: PROLOGUE-FREE softmax: one block per (bs,p) plane,
// read-once, all 10 k in registers. Index algebra: yb = 4*lane
// (thread-invariant) and xf = w + 16*j, so sy/sx fold out of
// the hot loop: accumulate se, J=sum(j*srow), U=sum(e1+2e2+3e3).
// Fused Huber; last block combines. grid (Pc, BSc) x 512.
// ============================================================
__global__ void __launch_bounds__(512)
softhub_kernel(const float* __restrict__ preds,
               const float* __restrict__ gt_sk,
               float* __restrict__ out) {
    int p  = blockIdx.x;
    int bs = blockIdx.y;
    int tid = threadIdx.x;
    int w = tid >> 5;
    int lane = tid & 31;
    int b  = bs >> 1;

    __shared__ float  stv[Kc];
    __shared__ int    spid[Kc];
    __shared__ float  swarp[16][3 * Kc];
    __shared__ float  tot[3 * Kc];
    __shared__ double shub[Kc];
    __shared__ int    isLast;
    __shared__ double dred[512];
    __shared__ double dred2[512];

    if (tid < Kc) {
        stv[tid]  = g_tv[bs * Kc + tid];
        spid[tid] = g_pid[bs * Kc + tid];
    }
    __syncthreads();

    const float4* __restrict__ hm4 = (const float4*)(preds + ((size_t)bs * Cc + p) * HWc);
    const float4* __restrict__ tg4 = hm4 + (Pc * HWc / 4);

    const float C1 = 4.328085122666891f;     // 3 * log2(e)
    const float C2 = 18.033688011112047f;    // 12.5 * log2(e)
    const float TWOC2 = 36.067376022224094f;
    float hmax = fmaxf(g_cand_v[(bs * NCH + 2 * p) * Kc],
                       g_cand_v[(bs * NCH + 2 * p + 1) * Kc]);
    float L = C1 * hmax;

    float tv[Kc], tvq[Kc];
#pragma unroll
    for (int k = 0; k < Kc; k++) {
        float t = stv[k];
        tv[k] = t;
        tvq[k] = -C2 * t * t;
    }

    // accumulators: se, J = sum j*srow, U = sum (e1 + 2e2 + 3e3)
    float se[Kc], J[Kc], U[Kc];
#pragma unroll
    for (int k = 0; k < Kc; k++) { se[k] = 0.0f; J[k] = 0.0f; U[k] = 0.0f; }

#pragma unroll 2
    for (int j = 0; j < 8; j++) {
        int idx4 = tid + 512 * j;
        float4 h = hm4[idx4];
        float4 t = tg4[idx4];
        float jf = (float)j;
        float b0 = fmaf(C1, h.x, -L), b1 = fmaf(C1, h.y, -L);
        float b2 = fmaf(C1, h.z, -L), b3 = fmaf(C1, h.w, -L);
        float A0 = fmaf(t.x * (-C2), t.x, b0), B0 = t.x * TWOC2;
        float A1 = fmaf(t.y * (-C2), t.y, b1), B1 = t.y * TWOC2;
        float A2_ = fmaf(t.z * (-C2), t.z, b2), B2 = t.z * TWOC2;
        float A3 = fmaf(t.w * (-C2), t.w, b3), B3 = t.w * TWOC2;
#pragma unroll
        for (int k = 0; k < Kc; k++) {
            float e0f = ex2(fmaf(B0, tv[k], A0) + tvq[k]);
            float e1f = ex2(fmaf(B1, tv[k], A1) + tvq[k]);
            float e2f = ex2(fmaf(B2, tv[k], A2_) + tvq[k]);
            float e3f = ex2(fmaf(B3, tv[k], A3) + tvq[k]);
            float srow = (e0f + e1f) + (e2f + e3f);
            se[k] += srow;
            J[k] = fmaf(srow, jf, J[k]);
            float u = fmaf(e2f, 2.0f, e1f);
            U[k] += fmaf(e3f, 3.0f, u);
        }
    }

    // fold invariants: xf = w + 16j ; yf = 4*lane + c
    float wf = (float)w;
    float ybf = (float)(4 * lane);
#pragma unroll
    for (int k = 0; k < Kc; k++) {
        float sx = fmaf(16.0f, J[k], wf * se[k]);
        float sy = fmaf(ybf, se[k], U[k]);
        J[k] = sx; U[k] = sy;
    }

#pragma unroll
    for (int o = 16; o > 0; o >>= 1) {
#pragma unroll
        for (int k = 0; k < Kc; k++) {
            se[k] += __shfl_xor_sync(0xffffffffu, se[k], o);
            J[k]  += __shfl_xor_sync(0xffffffffu, J[k], o);
            U[k]  += __shfl_xor_sync(0xffffffffu, U[k], o);
        }
    }
    if (lane == 0) {
#pragma unroll
        for (int k = 0; k < Kc; k++) {
            swarp[w][k]          = se[k];
            swarp[w][Kc + k]     = J[k];
            swarp[w][2 * Kc + k] = U[k];
        }
    }
    __syncthreads();
    if (tid < 3 * Kc) {
        float s = 0.0f;
#pragma unroll
        for (int ww = 0; ww < 16; ww++) s += swarp[ww][tid];
        tot[tid] = s;
    }
    __syncthreads();

    // Huber for all 10 ks
    if (tid < Kc) {
        float seT = tot[tid], sxT = tot[Kc + tid], syT = tot[2 * Kc + tid];
        float inv = 1.0f / seT;
        float px = sxT * inv, py = syT * inv;
        int pid = spid[tid];
        const float* sk = gt_sk + ((b * Mc + pid) * Pc + p) * 3;
        float ex = sk[0] - px;
        float ey = sk[1] - py;
        float err = sqrtf(ex * ex + ey * ey + 1e-12f) * ((sk[2] > 0.0f) ? 1.0f : 0.0f);
        float a = fabsf(err);
        shub[tid] = (double)((a < 0.1f) ? (err * err) : (0.1f * (a - 0.05f)));
    }
    __syncthreads();
    if (tid == 0) {
        double s = 0.0;
#pragma unroll
        for (int k = 0; k < Kc; k++) s += shub[k];
        g_hubpart[bs * Pc + p] = s;
    }

    // ---- last block: final combine (incl. det partial sum) ----
    __threadfence();
    if (tid == 0) isLast = (atomicAdd(&g_cnt2, 1) == PLN - 1) ? 1 : 0;
    __syncthreads();
    if (!isLast) return;
    __threadfence();

    double hacc = 0.0, dacc = 0.0;
    for (int j = tid; j < PLN; j += 512) hacc += g_hubpart[j];
    for (int j = tid; j < BSc * NCH; j += 512) dacc += g_det_part[j];
    dred[tid] = hacc;
    dred2[tid] = dacc;
    __syncthreads();
    for (int o = 256; o > 0; o >>= 1) {
        if (tid < o) { dred[tid] += dred[tid + o]; dred2[tid] += dred2[tid + o]; }
        __syncthreads();
    }
    if (tid == 0) {
        double det = dred2[0] / (double)DET_N;
        double total = g_pushpull[0] / 8.0
                     + g_pushpull[1] / 8.0
                     + det
                     + 10.0 * dred[0] / (double)NITEM;
        out[0] = (float)total;
        g_cnt2 = 0;           // reset for graph replay
    }
}

// ============================================================
extern "C" void kernel_launch(void* const* d_in, const int* in_sizes, int n_in,
                              void* d_out, int out_size) {
    const float* preds       = (const float*)d_in[0];
    const float* gt_masks    = (const float*)d_in[1];
    const float* gt_heatmaps = (const float*)d_in[2];
    const float* gt_sk       = (const float*)d_in[3];
    const int*   gt_kp       = (const int*)d_in[4];

    scan_kernel<<<dim3(NCH, BSc), 512>>>(preds, gt_masks, gt_heatmaps);
    aux_kernel<<<1, 512>>>(preds, gt_sk, gt_kp);
    softhub_kernel<<<dim3(Pc, BSc), 512>>>(preds, gt_sk, (float*)d_out);
}

// round 14
// speedup vs baseline: 1.0685x; 1.0041x over previous
#include <cuda_runtime.h>
#include <math.h>

#define Bc 4
#define Sc 2
#define Pc 17
#define Wc 128
#define Mc 8
#define Kc 10
#define Cc 34          // (1+TAG)*P
#define HWc 16384
#define BSc 8
#define DET_N (Bc*Sc*Pc*HWc)
#define NITEM (BSc*Kc*Pc)   // 1360
#define PLN (Pc*BSc)        // 136 planes
#define NCAND (Pc*Kc)       // 170 candidates per bs

// ---------------- scratch (device globals) ----------------
__device__ double g_det_part[PLN];
__device__ float  g_cand_v[BSc*NCAND];
__device__ int    g_cand_i[BSc*NCAND];
__device__ float  g_tv[BSc*Kc];
__device__ int    g_pid[BSc*Kc];
__device__ double g_hubpart[PLN];
__device__ double g_pushpull[2];
__device__ int    g_cnt2 = 0;

#define EINV 0.36787944117144233f

// single-MUFU exp2
__device__ __forceinline__ float ex2(float x) {
    float r;
    asm("ex2.approx.ftz.f32 %0, %1;" : "=f"(r) : "f"(x));
    return r;
}

// monotone float -> orderable uint
__device__ __forceinline__ unsigned ford(float f) {
    unsigned b = __float_as_uint(f);
    return b ^ ((b & 0x80000000u) ? 0xFFFFFFFFu : 0x80000000u);
}

// branchless register-resident top-10 insertion (descending sorted)
__device__ __forceinline__ void insert10(float val, int idx, float* v, int* ix) {
    if (val <= v[Kc - 1]) return;
#pragma unroll
    for (int k = Kc - 1; k > 0; k--) {
        bool shift = val > v[k - 1];
        bool place = val > v[k];
        float nv = shift ? v[k - 1] : (place ? val : v[k]);
        int   ni = shift ? ix[k - 1] : (place ? idx : ix[k]);
        v[k] = nv; ix[k] = ni;
    }
    if (val > v[0]) { v[0] = val; ix[0] = idx; }
}

// ============================================================
// Kernel 1: top-10 candidates per (bs,p) plane — NO BCE here.
// grid (Pc, BSc) = 136 blocks x 512 threads; 32 elems/thread.
// ============================================================
__global__ void __launch_bounds__(512)
topk_kernel(const float* __restrict__ preds) {
    int p  = blockIdx.x;
    int bs = blockIdx.y;
    int tid = threadIdx.x;
    int w = tid >> 5;
    int lane = tid & 31;

    const float4* __restrict__ hm4 = (const float4*)(preds + ((size_t)bs * Cc + p) * HWc);
    int i0 = p * HWc;

    float v[Kc]; int ix[Kc];
#pragma unroll
    for (int k = 0; k < Kc; k++) { v[k] = -3.0e38f; ix[k] = -1; }

#pragma unroll
    for (int j = 0; j < 8; j++) {
        int idx4 = tid + 512 * j;
        float4 f = hm4[idx4];
        // quad gate: skip all 4 compares unless one can enter
        float m01 = fmaxf(f.x, f.y), m23 = fmaxf(f.z, f.w);
        if (fmaxf(m01, m23) > v[Kc - 1]) {
            int e = i0 + 4 * idx4;
            insert10(f.x, e + 0, v, ix);
            insert10(f.y, e + 1, v, ix);
            insert10(f.z, e + 2, v, ix);
            insert10(f.w, e + 3, v, ix);
        }
    }

    // per-warp top-10 via redux argmax (no barriers)
    __shared__ float swv[160];
    __shared__ int   swi[160];
    for (int sel = 0; sel < Kc; sel++) {
        float bv = v[0]; int bidx = ix[0]; int bslot = 0;
#pragma unroll
        for (int j = 1; j < Kc; j++)
            if (v[j] > bv) { bv = v[j]; bidx = ix[j]; bslot = j; }
        unsigned ub = ford(bv);
        unsigned mx = __reduce_max_sync(0xffffffffu, ub);
        unsigned msk = __ballot_sync(0xffffffffu, ub == mx);
        int leader = __ffs(msk) - 1;
        if (lane == leader) {
            swv[w * Kc + sel] = bv;
            swi[w * Kc + sel] = bidx;
#pragma unroll
            for (int j = 0; j < Kc; j++)
                if (j == bslot) v[j] = -3.1e38f;
        }
    }
    __syncthreads();

    // warp 0: merge 160 candidates -> plane top-10
    if (w == 0) {
        float cv[5]; int ci[5];
#pragma unroll
        for (int t = 0; t < 5; t++) {
            cv[t] = swv[lane * 5 + t];
            ci[t] = swi[lane * 5 + t];
        }
        for (int sel = 0; sel < Kc; sel++) {
            float bv = cv[0]; int bidx = ci[0]; int bslot = 0;
#pragma unroll
            for (int t = 1; t < 5; t++)
                if (cv[t] > bv) { bv = cv[t]; bidx = ci[t]; bslot = t; }
            unsigned ub = ford(bv);
            unsigned mx = __reduce_max_sync(0xffffffffu, ub);
            unsigned msk = __ballot_sync(0xffffffffu, ub == mx);
            int leader = __ffs(msk) - 1;
            if (lane == leader) {
                int slot = (bs * Pc + p) * Kc + sel;
                g_cand_v[slot] = bv;
                g_cand_i[slot] = bidx;
#pragma unroll
                for (int t = 0; t < 5; t++)
                    if (t == bslot) cv[t] = -3.1e38f;
            }
        }
    }
}

// ============================================================
// Kernel 2 (tiny): aux — redux merge per bs (warps 0-7),
// push/pull (warps 8-15), then tv & person_ids.
// ============================================================
__global__ void __launch_bounds__(512)
aux_kernel(const float* __restrict__ preds,
           const float* __restrict__ gt_sk,
           const int* __restrict__ gt_kp) {
    int tid = threadIdx.x;
    int w = tid >> 5;
    int lane = tid & 31;
    __shared__ int   stopi[BSc * Kc];
    __shared__ float spush[BSc], spull[BSc];

    if (w < BSc) {
        // ---- redux merge: 170 candidates -> top-10 for bs = w ----
        int mbs = w;
        float cv[6]; int ci[6];
#pragma unroll
        for (int j = 0; j < 6; j++) {
            int c = lane * 6 + j;
            if (c < NCAND) {
                cv[j] = g_cand_v[mbs * NCAND + c];
                ci[j] = g_cand_i[mbs * NCAND + c];
            } else { cv[j] = -3.3e38f; ci[j] = -1; }
        }
        for (int sel = 0; sel < Kc; sel++) {
            float bv = cv[0]; int bidx = ci[0]; int bslot = 0;
#pragma unroll
            for (int j = 1; j < 6; j++)
                if (cv[j] > bv) { bv = cv[j]; bidx = ci[j]; bslot = j; }
            unsigned ub = ford(bv);
            unsigned mx = __reduce_max_sync(0xffffffffu, ub);
            unsigned msk = __ballot_sync(0xffffffffu, ub == mx);
            int leader = __ffs(msk) - 1;
            if (lane == leader) {
                stopi[mbs * Kc + sel] = bidx;
#pragma unroll
                for (int j = 0; j < 6; j++)
                    if (j == bslot) cv[j] = -3.3e38f;
            }
        }
    } else {
        // ---- push/pull for bs = w-8 (lane = m*4 + q) ----
        int mbs = w - BSc;
        int mb  = mbs / Sc;
        int m  = lane >> 2;
        int q  = lane & 3;
        int np = (q == 0) ? 5 : 4;
        const float* tb = preds + ((size_t)mbs * Cc + Pc) * HWc;
        const int* kpb = gt_kp + ((mb * Mc + m) * Pc) * 2;

        float gv[5], vv[5];
        float cnt = 0.0f, sum = 0.0f;
#pragma unroll
        for (int i = 0; i < 5; i++) {
            gv[i] = 0.0f; vv[i] = 0.0f;
            if (i < np) {
                int pp2 = q + 4 * i;
                int idx  = kpb[2 * pp2];
                float vis = (kpb[2 * pp2 + 1] > 0) ? 1.0f : 0.0f;
                float g = tb[idx];
                gv[i] = g; vv[i] = vis;
                cnt += vis; sum += vis * g;
            }
        }
        cnt += __shfl_xor_sync(0xffffffffu, cnt, 1);
        cnt += __shfl_xor_sync(0xffffffffu, cnt, 2);
        sum += __shfl_xor_sync(0xffffffffu, sum, 1);
        sum += __shfl_xor_sync(0xffffffffu, sum, 2);
        float valid = (cnt > 0.0f) ? 1.0f : 0.0f;
        float safe  = fmaxf(cnt, 1.0f);
        float mean  = sum / safe;
        float pp = 0.0f;
#pragma unroll
        for (int i = 0; i < 5; i++) {
            float d = gv[i] - mean;
            pp += d * d * vv[i];
        }
        pp += __shfl_xor_sync(0xffffffffu, pp, 1);
        pp += __shfl_xor_sync(0xffffffffu, pp, 2);
        float pull_m = (pp / safe) * valid;
        float num = valid, pullsum = pull_m;
#pragma unroll
        for (int o = 4; o <= 16; o <<= 1) {
            num     += __shfl_xor_sync(0xffffffffu, num, o);
            pullsum += __shfl_xor_sync(0xffffffffu, pullsum, o);
        }
        float rowsum = 0.0f;
#pragma unroll
        for (int jj = 0; jj < 2; jj++) {
            int j = q + 4 * jj;
            float mj = __shfl_sync(0xffffffffu, mean, j * 4);
            float vj = __shfl_sync(0xffffffffu, valid, j * 4);
            float d = mean - mj;
            rowsum += __expf(-d * d) * valid * vj;
        }
        rowsum += __shfl_xor_sync(0xffffffffu, rowsum, 1);
        rowsum += __shfl_xor_sync(0xffffffffu, rowsum, 2);
        float pmsum = rowsum;
#pragma unroll
        for (int o = 4; o <= 16; o <<= 1)
            pmsum += __shfl_xor_sync(0xffffffffu, pmsum, o);
        if (lane == 0) {
            spush[mbs] = (pmsum - num) / ((num - 1.0f) * num + 1e-6f) * 0.5f;
            spull[mbs] = pullsum / (num + 1e-6f);
        }
    }
    __syncthreads();

    // ---- tv & person_ids ----
    if (tid < BSc * Kc) {
        int tbs = tid / Kc;
        int tb  = tbs / Sc;
        int i  = stopi[tid];
        int tp = i / HWc;
        int hw = i % HWc;
        int xi = hw / Wc;
        int yi = hw % Wc;
        g_tv[tid] = preds[((size_t)tbs * Cc + Pc) * HWc + i];
        float best = 3.4e38f; int bestm = 0;
        for (int m = 0; m < Mc; m++) {
            const float* sk = gt_sk + ((tb * Mc + m) * Pc + tp) * 3;
            float vp = (sk[2] == 1.0f) ? 256.0f : 0.0f;
            float d0 = vp + sk[1] - (float)xi;
            float d1 = vp + sk[2] - (float)yi;
            float d  = sqrtf(d0 * d0 + d1 * d1 + 1e-12f);
            if (d < best) { best = d; bestm = m; }
        }
        g_pid[tid] = bestm;
    }
    if (tid == 128) {
        double sp = 0.0, sl = 0.0;
        for (int j = 0; j < BSc; j++) { sp += (double)spush[j]; sl += (double)spull[j]; }
        g_pushpull[0] = sp;
        g_pushpull[1] = sl;
    }
}

// ============================================================
// Kernel 3: softmax + BCE fused, one block per (bs,p) plane.
// Read-once softmax (10 k in regs, folded coords) interleaved
// with BCE over the same plane (fills stall bubbles).
// Fused Huber; last block combines. grid (Pc, BSc) x 512.
// ============================================================
__global__ void __launch_bounds__(512)
softhub_kernel(const float* __restrict__ preds,
               const float* __restrict__ gt_masks,
               const float* __restrict__ gt_heatmaps,
               const float* __restrict__ gt_sk,
               float* __restrict__ out) {
    int p  = blockIdx.x;
    int bs = blockIdx.y;
    int tid = threadIdx.x;
    int w = tid >> 5;
    int lane = tid & 31;
    int b  = bs >> 1;

    __shared__ float  stv[Kc];
    __shared__ int    spid[Kc];
    __shared__ float  swarp[16][3 * Kc];
    __shared__ float  sdet[16];
    __shared__ float  tot[3 * Kc];
    __shared__ double shub[Kc];
    __shared__ int    isLast;
    __shared__ double dred[512];
    __shared__ double dred2[512];

    if (tid < Kc) {
        stv[tid]  = g_tv[bs * Kc + tid];
        spid[tid] = g_pid[bs * Kc + tid];
    }
    __syncthreads();

    const float4* __restrict__ hm4 = (const float4*)(preds + ((size_t)bs * Cc + p) * HWc);
    const float4* __restrict__ tg4 = hm4 + (Pc * HWc / 4);
    const float4* __restrict__ gh4 = (const float4*)(gt_heatmaps + ((size_t)(b * Pc + p)) * HWc);
    const float4* __restrict__ mk4 = (const float4*)(gt_masks + (size_t)b * HWc);

    const float C1 = 4.328085122666891f;     // 3 * log2(e)
    const float C2 = 18.033688011112047f;    // 12.5 * log2(e)
    const float TWOC2 = 36.067376022224094f;
    float L = C1 * g_cand_v[(bs * Pc + p) * Kc];   // plane max of hm

    float tv[Kc], tvq[Kc];
#pragma unroll
    for (int k = 0; k < Kc; k++) {
        float t = stv[k];
        tv[k] = t;
        tvq[k] = -C2 * t * t;
    }

    // accumulators: se, J = sum j*srow, U = sum (e1 + 2e2 + 3e3); BCE facc
    float se[Kc], J[Kc], U[Kc];
#pragma unroll
    for (int k = 0; k < Kc; k++) { se[k] = 0.0f; J[k] = 0.0f; U[k] = 0.0f; }
    float facc = 0.0f;

#pragma unroll 2
    for (int j = 0; j < 8; j++) {
        int idx4 = tid + 512 * j;
        float4 h = hm4[idx4];
        float4 t = tg4[idx4];
        float4 g = gh4[idx4];
        float4 mk = mk4[idx4];
        float jf = (float)j;

        // ---- BCE over the 4 elements ----
        {
            float hs[4] = {h.x, h.y, h.z, h.w};
            float gs[4] = {g.x, g.y, g.z, g.w};
            float ms[4] = {mk.x, mk.y, mk.z, mk.w};
#pragma unroll
            for (int c = 0; c < 4; c++) {
                float prob = __fdividef(1.0f, 1.0f + __expf(-hs[c]));
                float x = prob * ms[c];
                bool selp = gs[c] > EINV;
                float wv  = selp ? 10.0f : ((gs[c] < EINV) ? 0.5f : 0.0f);
                float arg = selp ? x : (1.0f - x);
                facc -= wv * fmaxf(__logf(arg), -100.0f);
            }
        }

        // ---- softmax terms ----
        float b0 = fmaf(C1, h.x, -L), b1 = fmaf(C1, h.y, -L);
        float b2 = fmaf(C1, h.z, -L), b3 = fmaf(C1, h.w, -L);
        float A0 = fmaf(t.x * (-C2), t.x, b0), B0 = t.x * TWOC2;
        float A1 = fmaf(t.y * (-C2), t.y, b1), B1 = t.y * TWOC2;
        float A2_ = fmaf(t.z * (-C2), t.z, b2), B2 = t.z * TWOC2;
        float A3 = fmaf(t.w * (-C2), t.w, b3), B3 = t.w * TWOC2;
#pragma unroll
        for (int k = 0; k < Kc; k++) {
            float e0f = ex2(fmaf(B0, tv[k], A0) + tvq[k]);
            float e1f = ex2(fmaf(B1, tv[k], A1) + tvq[k]);
            float e2f = ex2(fmaf(B2, tv[k], A2_) + tvq[k]);
            float e3f = ex2(fmaf(B3, tv[k], A3) + tvq[k]);
            float srow = (e0f + e1f) + (e2f + e3f);
            se[k] += srow;
            J[k] = fmaf(srow, jf, J[k]);
            float u = fmaf(e2f, 2.0f, e1f);
            U[k] += fmaf(e3f, 3.0f, u);
        }
    }

    // BCE warp reduce -> sdet
#pragma unroll
    for (int o = 16; o > 0; o >>= 1) facc += __shfl_xor_sync(0xffffffffu, facc, o);
    if (lane == 0) sdet[w] = facc;

    // fold invariants: xf = w + 16j ; yf = 4*lane + c
    float wf = (float)w;
    float ybf = (float)(4 * lane);
#pragma unroll
    for (int k = 0; k < Kc; k++) {
        float sx = fmaf(16.0f, J[k], wf * se[k]);
        float sy = fmaf(ybf, se[k], U[k]);
        J[k] = sx; U[k] = sy;
    }

#pragma unroll
    for (int o = 16; o > 0; o >>= 1) {
#pragma unroll
        for (int k = 0; k < Kc; k++) {
            se[k] += __shfl_xor_sync(0xffffffffu, se[k], o);
            J[k]  += __shfl_xor_sync(0xffffffffu, J[k], o);
            U[k]  += __shfl_xor_sync(0xffffffffu, U[k], o);
        }
    }
    if (lane == 0) {
#pragma unroll
        for (int k = 0; k < Kc; k++) {
            swarp[w][k]          = se[k];
            swarp[w][Kc + k]     = J[k];
            swarp[w][2 * Kc + k] = U[k];
        }
    }
    __syncthreads();
    if (tid < 3 * Kc) {
        float s = 0.0f;
#pragma unroll
        for (int ww = 0; ww < 16; ww++) s += swarp[ww][tid];
        tot[tid] = s;
    }
    if (tid == 32) {
        double d = 0.0;
#pragma unroll
        for (int ww = 0; ww < 16; ww++) d += (double)sdet[ww];
        g_det_part[bs * Pc + p] = d;
    }
    __syncthreads();

    // Huber for all 10 ks
    if (tid < Kc) {
        float seT = tot[tid], sxT = tot[Kc + tid], syT = tot[2 * Kc + tid];
        float inv = 1.0f / seT;
        float px = sxT * inv, py = syT * inv;
        int pid = spid[tid];
        const float* sk = gt_sk + ((b * Mc + pid) * Pc + p) * 3;
        float ex = sk[0] - px;
        float ey = sk[1] - py;
        float err = sqrtf(ex * ex + ey * ey + 1e-12f) * ((sk[2] > 0.0f) ? 1.0f : 0.0f);
        float a = fabsf(err);
        shub[tid] = (double)((a < 0.1f) ? (err * err) : (0.1f * (a - 0.05f)));
    }
    __syncthreads();
    if (tid == 0) {
        double s = 0.0;
#pragma unroll
        for (int k = 0; k < Kc; k++) s += shub[k];
        g_hubpart[bs * Pc + p] = s;
    }

    // ---- last block: final combine ----
    __threadfence();
    if (tid == 0) isLast = (atomicAdd(&g_cnt2, 1) == PLN - 1) ? 1 : 0;
    __syncthreads();
    if (!isLast) return;
    __threadfence();

    double hacc = 0.0, dacc = 0.0;
    for (int j = tid; j < PLN; j += 512) { hacc += g_hubpart[j]; dacc += g_det_part[j]; }
    dred[tid] = hacc;
    dred2[tid] = dacc;
    __syncthreads();
    for (int o = 256; o > 0; o >>= 1) {
        if (tid < o) { dred[tid] += dred[tid + o]; dred2[tid] += dred2[tid + o]; }
        __syncthreads();
    }
    if (tid == 0) {
        double det = dred2[0] / (double)DET_N;
        double total = g_pushpull[0] / 8.0
                     + g_pushpull[1] / 8.0
                     + det
                     + 10.0 * dred[0] / (double)NITEM;
        out[0] = (float)total;
        g_cnt2 = 0;           // reset for graph replay
    }
}

// ============================================================
extern "C" void kernel_launch(void* const* d_in, const int* in_sizes, int n_in,
                              void* d_out, int out_size) {
    const float* preds       = (const float*)d_in[0];
    const float* gt_masks    = (const float*)d_in[1];
    const float* gt_heatmaps = (const float*)d_in[2];
    const float* gt_sk       = (const float*)d_in[3];
    const int*   gt_kp       = (const int*)d_in[4];

    topk_kernel<<<dim3(Pc, BSc), 512>>>(preds);
    aux_kernel<<<1, 512>>>(preds, gt_sk, gt_kp);
    softhub_kernel<<<dim3(Pc, BSc), 512>>>(preds, gt_masks, gt_heatmaps, gt_sk, (float*)d_out);
}

// round 15
// speedup vs baseline: 1.1791x; 1.1035x over previous
#include <cuda_runtime.h>
#include <math.h>

#define Bc 4
#define Sc 2
#define Pc 17
#define Wc 128
#define Mc 8
#define Kc 10
#define Cc 34          // (1+TAG)*P
#define HWc 16384
#define BSc 8
#define DET_N (Bc*Sc*Pc*HWc)
#define NCH 34
#define CHUNK 8192
#define NITEM (BSc*Kc*Pc)   // 1360
#define PLN (Pc*BSc)        // 136 planes

// ---------------- scratch (device globals) ----------------
__device__ double g_det_part[PLN];
__device__ float  g_cand_v[BSc*NCH*Kc];
__device__ int    g_cand_i[BSc*NCH*Kc];
__device__ float  g_tv[BSc*Kc];
__device__ int    g_pid[BSc*Kc];
__device__ double g_hubpart[PLN];
__device__ double g_pushpull[2];
__device__ int    g_cnt2 = 0;

#define EINV 0.36787944117144233f

// single-MUFU exp2
__device__ __forceinline__ float ex2(float x) {
    float r;
    asm("ex2.approx.ftz.f32 %0, %1;" : "=f"(r) : "f"(x));
    return r;
}

// monotone float -> orderable uint
__device__ __forceinline__ unsigned ford(float f) {
    unsigned b = __float_as_uint(f);
    return b ^ ((b & 0x80000000u) ? 0xFFFFFFFFu : 0x80000000u);
}

// ============================================================
// Kernel 1: top-10 per (bs, half-plane chunk) — FMAX-chain +
// lazy-rescan extraction (no sorted insertion, minimal ALU).
// grid (NCH, BSc) = 272 blocks x 512 threads; 16 elems/thread
// held in registers.
// ============================================================
__global__ void __launch_bounds__(512, 2)
topk_kernel(const float* __restrict__ preds) {
    int ch = blockIdx.x;            // 0..33 : p = ch>>1, half = ch&1
    int bs = blockIdx.y;
    int tid = threadIdx.x;
    int w = tid >> 5;
    int lane = tid & 31;
    int p   = ch >> 1;
    int hw0 = (ch & 1) * CHUNK;

    const float4* __restrict__ hm4 =
        (const float4*)(preds + ((size_t)bs * Cc + p) * HWc + hw0);
    int i0 = p * HWc + hw0;

    // load 16 elements into registers; running max via FMAX (fma pipe)
    float fr[16];
#pragma unroll
    for (int j = 0; j < 4; j++) {
        float4 f = hm4[tid + 512 * j];
        fr[4 * j]     = f.x;
        fr[4 * j + 1] = f.y;
        fr[4 * j + 2] = f.z;
        fr[4 * j + 3] = f.w;
    }
    float tm = fr[0];
#pragma unroll
    for (int i = 1; i < 16; i++) tm = fmaxf(tm, fr[i]);

    __shared__ float swm[16];
    __shared__ float scur;
    __shared__ int   swin;

    // init per-warp maxes
    {
        float wm = tm;
#pragma unroll
        for (int o = 16; o > 0; o >>= 1) wm = fmaxf(wm, __shfl_xor_sync(0xffffffffu, wm, o));
        if (lane == 0) swm[w] = wm;
    }
    __syncthreads();

    for (int sel = 0; sel < Kc; sel++) {
        if (tid == 0) {
            float bb = swm[0]; int bw = 0;
#pragma unroll
            for (int j = 1; j < 16; j++)
                if (swm[j] > bb) { bb = swm[j]; bw = j; }
            scur = bb; swin = bw;
        }
        __syncthreads();
        float cur = scur;
        if (w == swin) {
            unsigned msk = __ballot_sync(0xffffffffu, tm == cur);
            int owner = __ffs(msk) - 1;
            if (lane == owner) {
                int slot = -1;
#pragma unroll
                for (int i = 0; i < 16; i++)
                    if (slot < 0 && fr[i] == cur) slot = i;
                int jj = slot >> 2, cc = slot & 3;
                int gslot = (bs * NCH + ch) * Kc + sel;
                g_cand_v[gslot] = cur;
                g_cand_i[gslot] = i0 + 4 * (tid + 512 * jj) + cc;
#pragma unroll
                for (int i = 0; i < 16; i++)
                    if (i == slot) fr[i] = -3.0e38f;
                float nm = fr[0];
#pragma unroll
                for (int i = 1; i < 16; i++) nm = fmaxf(nm, fr[i]);
                tm = nm;
            }
            // refresh this warp's max
            float wm = tm;
#pragma unroll
            for (int o = 16; o > 0; o >>= 1) wm = fmaxf(wm, __shfl_xor_sync(0xffffffffu, wm, o));
            if (lane == 0) swm[w] = wm;
        }
        __syncthreads();
    }
}

// ============================================================
// Kernel 2 (tiny): aux — redux merge per bs (warps 0-7, 340
// candidates), push/pull (warps 8-15), then tv & person_ids.
// ============================================================
__global__ void __launch_bounds__(512)
aux_kernel(const float* __restrict__ preds,
           const float* __restrict__ gt_sk,
           const int* __restrict__ gt_kp) {
    int tid = threadIdx.x;
    int w = tid >> 5;
    int lane = tid & 31;
    __shared__ int   stopi[BSc * Kc];
    __shared__ float spush[BSc], spull[BSc];

    if (w < BSc) {
        // ---- redux merge: 340 candidates -> top-10 for bs = w ----
        int mbs = w;
        float cv[11]; int ci[11];
#pragma unroll
        for (int j = 0; j < 11; j++) {
            int c = lane * 11 + j;
            if (c < NCH * Kc) {
                cv[j] = g_cand_v[mbs * NCH * Kc + c];
                ci[j] = g_cand_i[mbs * NCH * Kc + c];
            } else { cv[j] = -3.3e38f; ci[j] = -1; }
        }
        for (int sel = 0; sel < Kc; sel++) {
            float bv = cv[0]; int bidx = ci[0]; int bslot = 0;
#pragma unroll
            for (int j = 1; j < 11; j++)
                if (cv[j] > bv) { bv = cv[j]; bidx = ci[j]; bslot = j; }
            unsigned ub = ford(bv);
            unsigned mx = __reduce_max_sync(0xffffffffu, ub);
            unsigned msk = __ballot_sync(0xffffffffu, ub == mx);
            int leader = __ffs(msk) - 1;
            if (lane == leader) {
                stopi[mbs * Kc + sel] = bidx;
#pragma unroll
                for (int j = 0; j < 11; j++)
                    if (j == bslot) cv[j] = -3.3e38f;
            }
        }
    } else {
        // ---- push/pull for bs = w-8 (lane = m*4 + q) ----
        int mbs = w - BSc;
        int mb  = mbs / Sc;
        int m  = lane >> 2;
        int q  = lane & 3;
        int np = (q == 0) ? 5 : 4;
        const float* tb = preds + ((size_t)mbs * Cc + Pc) * HWc;
        const int* kpb = gt_kp + ((mb * Mc + m) * Pc) * 2;

        float gv[5], vv[5];
        float cnt = 0.0f, sum = 0.0f;
#pragma unroll
        for (int i = 0; i < 5; i++) {
            gv[i] = 0.0f; vv[i] = 0.0f;
            if (i < np) {
                int pp2 = q + 4 * i;
                int idx  = kpb[2 * pp2];
                float vis = (kpb[2 * pp2 + 1] > 0) ? 1.0f : 0.0f;
                float g = tb[idx];
                gv[i] = g; vv[i] = vis;
                cnt += vis; sum += vis * g;
            }
        }
        cnt += __shfl_xor_sync(0xffffffffu, cnt, 1);
        cnt += __shfl_xor_sync(0xffffffffu, cnt, 2);
        sum += __shfl_xor_sync(0xffffffffu, sum, 1);
        sum += __shfl_xor_sync(0xffffffffu, sum, 2);
        float valid = (cnt > 0.0f) ? 1.0f : 0.0f;
        float safe  = fmaxf(cnt, 1.0f);
        float mean  = sum / safe;
        float pp = 0.0f;
#pragma unroll
        for (int i = 0; i < 5; i++) {
            float d = gv[i] - mean;
            pp += d * d * vv[i];
        }
        pp += __shfl_xor_sync(0xffffffffu, pp, 1);
        pp += __shfl_xor_sync(0xffffffffu, pp, 2);
        float pull_m = (pp / safe) * valid;
        float num = valid, pullsum = pull_m;
#pragma unroll
        for (int o = 4; o <= 16; o <<= 1) {
            num     += __shfl_xor_sync(0xffffffffu, num, o);
            pullsum += __shfl_xor_sync(0xffffffffu, pullsum, o);
        }
        float rowsum = 0.0f;
#pragma unroll
        for (int jj = 0; jj < 2; jj++) {
            int j = q + 4 * jj;
            float mj = __shfl_sync(0xffffffffu, mean, j * 4);
            float vj = __shfl_sync(0xffffffffu, valid, j * 4);
            float d = mean - mj;
            rowsum += __expf(-d * d) * valid * vj;
        }
        rowsum += __shfl_xor_sync(0xffffffffu, rowsum, 1);
        rowsum += __shfl_xor_sync(0xffffffffu, rowsum, 2);
        float pmsum = rowsum;
#pragma unroll
        for (int o = 4; o <= 16; o <<= 1)
            pmsum += __shfl_xor_sync(0xffffffffu, pmsum, o);
        if (lane == 0) {
            spush[mbs] = (pmsum - num) / ((num - 1.0f) * num + 1e-6f) * 0.5f;
            spull[mbs] = pullsum / (num + 1e-6f);
        }
    }
    __syncthreads();

    // ---- tv & person_ids ----
    if (tid < BSc * Kc) {
        int tbs = tid / Kc;
        int tb  = tbs / Sc;
        int i  = stopi[tid];
        int tp = i / HWc;
        int hw = i % HWc;
        int xi = hw / Wc;
        int yi = hw % Wc;
        g_tv[tid] = preds[((size_t)tbs * Cc + Pc) * HWc + i];
        float best = 3.4e38f; int bestm = 0;
        for (int m = 0; m < Mc; m++) {
            const float* sk = gt_sk + ((tb * Mc + m) * Pc + tp) * 3;
            float vp = (sk[2] == 1.0f) ? 256.0f : 0.0f;
            float d0 = vp + sk[1] - (float)xi;
            float d1 = vp + sk[2] - (float)yi;
            float d  = sqrtf(d0 * d0 + d1 * d1 + 1e-12f);
            if (d < best) { best = d; bestm = m; }
        }
        g_pid[tid] = bestm;
    }
    if (tid == 128) {
        double sp = 0.0, sl = 0.0;
        for (int j = 0; j < BSc; j++) { sp += (double)spush[j]; sl += (double)spull[j]; }
        g_pushpull[0] = sp;
        g_pushpull[1] = sl;
    }
}

// ============================================================
// Kernel 3: softmax + BCE fused, one block per (bs,p) plane.
// (R14-proven body.) Fused Huber; last block combines.
// grid (Pc, BSc) x 512.
// ============================================================
__global__ void __launch_bounds__(512)
softhub_kernel(const float* __restrict__ preds,
               const float* __restrict__ gt_masks,
               const float* __restrict__ gt_heatmaps,
               const float* __restrict__ gt_sk,
               float* __restrict__ out) {
    int p  = blockIdx.x;
    int bs = blockIdx.y;
    int tid = threadIdx.x;
    int w = tid >> 5;
    int lane = tid & 31;
    int b  = bs >> 1;

    __shared__ float  stv[Kc];
    __shared__ int    spid[Kc];
    __shared__ float  swarp[16][3 * Kc];
    __shared__ float  sdet[16];
    __shared__ float  tot[3 * Kc];
    __shared__ double shub[Kc];
    __shared__ int    isLast;
    __shared__ double dred[512];
    __shared__ double dred2[512];

    if (tid < Kc) {
        stv[tid]  = g_tv[bs * Kc + tid];
        spid[tid] = g_pid[bs * Kc + tid];
    }
    __syncthreads();

    const float4* __restrict__ hm4 = (const float4*)(preds + ((size_t)bs * Cc + p) * HWc);
    const float4* __restrict__ tg4 = hm4 + (Pc * HWc / 4);
    const float4* __restrict__ gh4 = (const float4*)(gt_heatmaps + ((size_t)(b * Pc + p)) * HWc);
    const float4* __restrict__ mk4 = (const float4*)(gt_masks + (size_t)b * HWc);

    const float C1 = 4.328085122666891f;     // 3 * log2(e)
    const float C2 = 18.033688011112047f;    // 12.5 * log2(e)
    const float TWOC2 = 36.067376022224094f;
    float hmax = fmaxf(g_cand_v[(bs * NCH + 2 * p) * Kc],
                       g_cand_v[(bs * NCH + 2 * p + 1) * Kc]);
    float L = C1 * hmax;

    float tv[Kc], tvq[Kc];
#pragma unroll
    for (int k = 0; k < Kc; k++) {
        float t = stv[k];
        tv[k] = t;
        tvq[k] = -C2 * t * t;
    }

    float se[Kc], J[Kc], U[Kc];
#pragma unroll
    for (int k = 0; k < Kc; k++) { se[k] = 0.0f; J[k] = 0.0f; U[k] = 0.0f; }
    float facc = 0.0f;

#pragma unroll 2
    for (int j = 0; j < 8; j++) {
        int idx4 = tid + 512 * j;
        float4 h = hm4[idx4];
        float4 t = tg4[idx4];
        float4 g = gh4[idx4];
        float4 mk = mk4[idx4];
        float jf = (float)j;

        // ---- BCE over the 4 elements ----
        {
            float hs[4] = {h.x, h.y, h.z, h.w};
            float gs[4] = {g.x, g.y, g.z, g.w};
            float ms[4] = {mk.x, mk.y, mk.z, mk.w};
#pragma unroll
            for (int c = 0; c < 4; c++) {
                float prob = __fdividef(1.0f, 1.0f + __expf(-hs[c]));
                float x = prob * ms[c];
                bool selp = gs[c] > EINV;
                float wv  = selp ? 10.0f : ((gs[c] < EINV) ? 0.5f : 0.0f);
                float arg = selp ? x : (1.0f - x);
                facc -= wv * fmaxf(__logf(arg), -100.0f);
            }
        }

        // ---- softmax terms ----
        float b0 = fmaf(C1, h.x, -L), b1 = fmaf(C1, h.y, -L);
        float b2 = fmaf(C1, h.z, -L), b3 = fmaf(C1, h.w, -L);
        float A0 = fmaf(t.x * (-C2), t.x, b0), B0 = t.x * TWOC2;
        float A1 = fmaf(t.y * (-C2), t.y, b1), B1 = t.y * TWOC2;
        float A2_ = fmaf(t.z * (-C2), t.z, b2), B2 = t.z * TWOC2;
        float A3 = fmaf(t.w * (-C2), t.w, b3), B3 = t.w * TWOC2;
#pragma unroll
        for (int k = 0; k < Kc; k++) {
            float e0f = ex2(fmaf(B0, tv[k], A0) + tvq[k]);
            float e1f = ex2(fmaf(B1, tv[k], A1) + tvq[k]);
            float e2f = ex2(fmaf(B2, tv[k], A2_) + tvq[k]);
            float e3f = ex2(fmaf(B3, tv[k], A3) + tvq[k]);
            float srow = (e0f + e1f) + (e2f + e3f);
            se[k] += srow;
            J[k] = fmaf(srow, jf, J[k]);
            float u = fmaf(e2f, 2.0f, e1f);
            U[k] += fmaf(e3f, 3.0f, u);
        }
    }

    // BCE warp reduce -> sdet
#pragma unroll
    for (int o = 16; o > 0; o >>= 1) facc += __shfl_xor_sync(0xffffffffu, facc, o);
    if (lane == 0) sdet[w] = facc;

    // fold invariants: xf = w + 16j ; yf = 4*lane + c
    float wf = (float)w;
    float ybf = (float)(4 * lane);
#pragma unroll
    for (int k = 0; k < Kc; k++) {
        float sx = fmaf(16.0f, J[k], wf * se[k]);
        float sy = fmaf(ybf, se[k], U[k]);
        J[k] = sx; U[k] = sy;
    }

#pragma unroll
    for (int o = 16; o > 0; o >>= 1) {
#pragma unroll
        for (int k = 0; k < Kc; k++) {
            se[k] += __shfl_xor_sync(0xffffffffu, se[k], o);
            J[k]  += __shfl_xor_sync(0xffffffffu, J[k], o);
            U[k]  += __shfl_xor_sync(0xffffffffu, U[k], o);
        }
    }
    if (lane == 0) {
#pragma unroll
        for (int k = 0; k < Kc; k++) {
            swarp[w][k]          = se[k];
            swarp[w][Kc + k]     = J[k];
            swarp[w][2 * Kc + k] = U[k];
        }
    }
    __syncthreads();
    if (tid < 3 * Kc) {
        float s = 0.0f;
#pragma unroll
        for (int ww = 0; ww < 16; ww++) s += swarp[ww][tid];
        tot[tid] = s;
    }
    if (tid == 32) {
        double d = 0.0;
#pragma unroll
        for (int ww = 0; ww < 16; ww++) d += (double)sdet[ww];
        g_det_part[bs * Pc + p] = d;
    }
    __syncthreads();

    // Huber for all 10 ks
    if (tid < Kc) {
        float seT = tot[tid], sxT = tot[Kc + tid], syT = tot[2 * Kc + tid];
        float inv = 1.0f / seT;
        float px = sxT * inv, py = syT * inv;
        int pid = spid[tid];
        const float* sk = gt_sk + ((b * Mc + pid) * Pc + p) * 3;
        float ex = sk[0] - px;
        float ey = sk[1] - py;
        float err = sqrtf(ex * ex + ey * ey + 1e-12f) * ((sk[2] > 0.0f) ? 1.0f : 0.0f);
        float a = fabsf(err);
        shub[tid] = (double)((a < 0.1f) ? (err * err) : (0.1f * (a - 0.05f)));
    }
    __syncthreads();
    if (tid == 0) {
        double s = 0.0;
#pragma unroll
        for (int k = 0; k < Kc; k++) s += shub[k];
        g_hubpart[bs * Pc + p] = s;
    }

    // ---- last block: final combine ----
    __threadfence();
    if (tid == 0) isLast = (atomicAdd(&g_cnt2, 1) == PLN - 1) ? 1 : 0;
    __syncthreads();
    if (!isLast) return;
    __threadfence();

    double hacc = 0.0, dacc = 0.0;
    for (int j = tid; j < PLN; j += 512) { hacc += g_hubpart[j]; dacc += g_det_part[j]; }
    dred[tid] = hacc;
    dred2[tid] = dacc;
    __syncthreads();
    for (int o = 256; o > 0; o >>= 1) {
        if (tid < o) { dred[tid] += dred[tid + o]; dred2[tid] += dred2[tid + o]; }
        __syncthreads();
    }
    if (tid == 0) {
        double det = dred2[0] / (double)DET_N;
        double total = g_pushpull[0] / 8.0
                     + g_pushpull[1] / 8.0
                     + det
                     + 10.0 * dred[0] / (double)NITEM;
        out[0] = (float)total;
        g_cnt2 = 0;           // reset for graph replay
    }
}

// ============================================================
extern "C" void kernel_launch(void* const* d_in, const int* in_sizes, int n_in,
                              void* d_out, int out_size) {
    const float* preds       = (const float*)d_in[0];
    const float* gt_masks    = (const float*)d_in[1];
    const float* gt_heatmaps = (const float*)d_in[2];
    const float* gt_sk       = (const float*)d_in[3];
    const int*   gt_kp       = (const int*)d_in[4];

    topk_kernel<<<dim3(NCH, BSc), 512>>>(preds);
    aux_kernel<<<1, 512>>>(preds, gt_sk, gt_kp);
    softhub_kernel<<<dim3(Pc, BSc), 512>>>(preds, gt_masks, gt_heatmaps, gt_sk, (float*)d_out);
}